// round 2
// baseline (speedup 1.0000x reference)
#include <cuda_runtime.h>
#include <cuda_bf16.h>
#include <cstdint>

#define UNITS 256
#define NUM_BUCKETS 501
#define LB (-17.0f)
#define UB (8.0f)
#define STEPF 0.05f
#define INV_STEP 20.0f
#define RESIDUE (-17.05f)

#define UPB 8                                 // units per block
#define GROUPS (UNITS / UPB)                  // 32
#define ROW_CHUNKS 32
#define TAB_PER_BLOCK (UPB * NUM_BUCKETS)     // 4008 float2 = 32064 B

// Precomputed table: per (unit, bucket):
//   .x = STEP * csum_exc[u][j] + RESIDUE + b[u]
//   .y = w[u][j] = relu(v[u][j])
__device__ float2 g_tab[UNITS * NUM_BUCKETS];

// ---------------------------------------------------------------------------
// Kernel A: build the per-(unit,bucket) table. One block per unit.
// ---------------------------------------------------------------------------
__global__ void build_table_kernel(const float* __restrict__ v,
                                   const float* __restrict__ b) {
    __shared__ float s[512];
    const int u = blockIdx.x;
    const int t = threadIdx.x;

    float w = 0.0f;
    if (t < NUM_BUCKETS) {
        w = fmaxf(v[u * NUM_BUCKETS + t], 0.0f);
    }
    s[t] = w;

    // inclusive scan (Hillis-Steele)
    #pragma unroll
    for (int off = 1; off < 512; off <<= 1) {
        __syncthreads();
        float add = (t >= off) ? s[t - off] : 0.0f;
        __syncthreads();
        s[t] += add;
    }
    __syncthreads();

    if (t < NUM_BUCKETS) {
        float inc = s[t];
        float exc = inc - w;           // exclusive cumsum
        float2 e;
        e.x = STEPF * exc + RESIDUE + b[u];
        e.y = w;
        g_tab[u * NUM_BUCKETS + t] = e;
    }
}

// ---------------------------------------------------------------------------
// Kernel B: unit-tiled main pass. Block owns 8 units; their table slice lives
// in shared memory. Gathers become LDS.64 (low conflict) instead of scattered
// global loads. x/out accesses are 32B-sector coalesced.
// grid = (GROUPS, ROW_CHUNKS); block = 256 threads.
// ---------------------------------------------------------------------------
__global__ void __launch_bounds__(256)
iso_main_kernel(const float* __restrict__ x,
                float* __restrict__ out,
                int rows_per_block) {
    __shared__ float2 tab[TAB_PER_BLOCK];   // 32064 B

    const int g   = blockIdx.x;             // unit group (0..31)
    const int c   = blockIdx.y;             // row chunk
    const int tid = threadIdx.x;

    // Stage this group's table slice (coalesced, L2 hits)
    const float2* gt = &g_tab[g * TAB_PER_BLOCK];
    #pragma unroll 4
    for (int i = tid; i < TAB_PER_BLOCK; i += 256)
        tab[i] = gt[i];
    __syncthreads();

    const int row0  = c * rows_per_block;
    const int half  = tid & 1;               // which float4 of the 8 units
    const int rbase = tid >> 1;              // 0..127
    const int ucol  = g * UPB + half * 4;    // column offset within x row
    const int ubase = half * 4;              // unit within block slice

    for (int r = rbase; r < rows_per_block; r += 128) {
        const int row = row0 + r;
        const float4 xv = *(const float4*)&x[row * UNITS + ucol];
        float xin[4] = {xv.x, xv.y, xv.z, xv.w};
        float oo[4];

        #pragma unroll
        for (int j = 0; j < 4; ++j) {
            const int u = ubase + j;
            float xc = fminf(fmaxf(xin[j], LB + 1e-9f), UB - 1e-9f);
            float t  = xc - LB + STEPF;              // in (0.05, 25.05)
            int idx  = (int)(t * INV_STEP);
            idx = min(idx, NUM_BUCKETS - 1);
            float delta = t - (float)idx * STEPF;

            float2 tw = tab[u * NUM_BUCKETS + idx];
            float logit = fmaf(delta, tw.y, tw.x);
            float e = __expf(-logit);
            oo[j] = __frcp_rn(1.0f + e);
        }

        *(float4*)&out[row * UNITS + ucol] =
            make_float4(oo[0], oo[1], oo[2], oo[3]);
    }
}

// ---------------------------------------------------------------------------
extern "C" void kernel_launch(void* const* d_in, const int* in_sizes, int n_in,
                              void* d_out, int out_size) {
    const float* x = (const float*)d_in[0];   // (65536, 256)
    const float* v = (const float*)d_in[1];   // (256, 501)
    const float* b = (const float*)d_in[2];   // (256,)
    float* out = (float*)d_out;

    // Build the (unit, bucket) table
    build_table_kernel<<<UNITS, 512>>>(v, b);

    const int total = in_sizes[0];            // 65536 * 256
    const int rows  = total / UNITS;          // 65536
    const int rows_per_block = rows / ROW_CHUNKS;   // 2048

    dim3 grid(GROUPS, ROW_CHUNKS);
    iso_main_kernel<<<grid, 256>>>(x, out, rows_per_block);
}

// round 4
// speedup vs baseline: 1.0705x; 1.0705x over previous
#include <cuda_runtime.h>
#include <cuda_bf16.h>
#include <cstdint>

#define UNITS 256
#define NUM_BUCKETS 501
#define LB (-17.0f)
#define UB (8.0f)
#define STEPF 0.05f
#define INV_STEP 20.0f
#define RESIDUE (-17.05f)

// Precomputed table: per (unit, bucket):
//   .x = STEP * csum_exc[u][j] + RESIDUE + b[u]
//   .y = w[u][j] = relu(v[u][j])
__device__ float2 g_tab[UNITS * NUM_BUCKETS];

// ---------------------------------------------------------------------------
// Kernel A: build the per-(unit,bucket) table. One block per unit.
// ---------------------------------------------------------------------------
__global__ void build_table_kernel(const float* __restrict__ v,
                                   const float* __restrict__ b) {
    __shared__ float s[512];
    const int u = blockIdx.x;
    const int t = threadIdx.x;

    float w = 0.0f;
    if (t < NUM_BUCKETS) {
        w = fmaxf(v[u * NUM_BUCKETS + t], 0.0f);
    }
    s[t] = w;

    // inclusive scan (Hillis-Steele)
    #pragma unroll
    for (int off = 1; off < 512; off <<= 1) {
        __syncthreads();
        float add = (t >= off) ? s[t - off] : 0.0f;
        __syncthreads();
        s[t] += add;
    }
    __syncthreads();

    if (t < NUM_BUCKETS) {
        float inc = s[t];
        float exc = inc - w;           // exclusive cumsum
        float2 e;
        e.x = STEPF * exc + RESIDUE + b[u];
        e.y = w;
        g_tab[u * NUM_BUCKETS + t] = e;
    }
}

// ---------------------------------------------------------------------------
// Kernel B: warp-transposed main pass.
// Each warp owns a 32x32 tile (32 rows x 32 units):
//   phase 1: coalesced float4 loads -> padded smem tile (8 iters x 4 rows)
//   phase 2: transposed read (lane = row), so each gather instruction hits
//            ONE unit's table with clustered indices (~6-8 cache lines
//            instead of 32) -> ~4x fewer L1 wavefronts
//   phase 3: coalesced float4 stores from smem
// Block = 8 warps; grid = (UNITS/32, rows/256).
// ---------------------------------------------------------------------------
__global__ void __launch_bounds__(256)
iso_main_kernel(const float* __restrict__ x,
                float* __restrict__ out) {
    __shared__ float s[8][32 * 33];          // 33-float padded rows, per warp

    const int lane = threadIdx.x & 31;
    const int wid  = threadIdx.x >> 5;
    float* st = s[wid];

    const int u0 = blockIdx.x * 32;          // unit group
    const int r0 = blockIdx.y * 256 + wid * 32;

    const int col  = (lane & 7) * 4;         // float4 column within tile
    const int rsub = lane >> 3;              // 0..3

    // Phase 1: coalesced load of the 32x32 tile into smem (natural layout).
    // Each iteration covers 4 rows; 8 iterations cover all 32 rows.
    #pragma unroll
    for (int i = 0; i < 8; ++i) {
        const int row = i * 4 + rsub;
        const float4 xv = *(const float4*)&x[(r0 + row) * UNITS + u0 + col];
        float* p = &st[row * 33 + col];
        p[0] = xv.x; p[1] = xv.y; p[2] = xv.z; p[3] = xv.w;
    }
    __syncwarp();

    // Phase 2: lane = row. Iterate units; all lanes gather the SAME unit's
    // table with normally-clustered indices.
    #pragma unroll 4
    for (int k = 0; k < 32; ++k) {
        const float xval = st[lane * 33 + k];   // bank = (lane*33+k)%32 = (lane+k)%32, conflict-free

        float xc = fminf(fmaxf(xval, LB + 1e-9f), UB - 1e-9f);
        float t  = xc - LB + STEPF;             // in (0.05, 25.05)
        int idx  = (int)(t * INV_STEP);
        idx = min(idx, NUM_BUCKETS - 1);
        float delta = t - (float)idx * STEPF;

        const float2 tw = __ldg(&g_tab[(u0 + k) * NUM_BUCKETS + idx]);
        const float logit = fmaf(delta, tw.y, tw.x);
        const float e = __expf(-logit);
        st[lane * 33 + k] = __frcp_rn(1.0f + e);
    }
    __syncwarp();

    // Phase 3: coalesced store of the tile (8 iters x 4 rows)
    #pragma unroll
    for (int i = 0; i < 8; ++i) {
        const int row = i * 4 + rsub;
        const float* p = &st[row * 33 + col];
        *(float4*)&out[(r0 + row) * UNITS + u0 + col] =
            make_float4(p[0], p[1], p[2], p[3]);
    }
}

// ---------------------------------------------------------------------------
extern "C" void kernel_launch(void* const* d_in, const int* in_sizes, int n_in,
                              void* d_out, int out_size) {
    const float* x = (const float*)d_in[0];   // (65536, 256)
    const float* v = (const float*)d_in[1];   // (256, 501)
    const float* b = (const float*)d_in[2];   // (256,)
    float* out = (float*)d_out;

    // Build the (unit, bucket) table
    build_table_kernel<<<UNITS, 512>>>(v, b);

    const int total = in_sizes[0];            // 65536 * 256
    const int rows  = total / UNITS;          // 65536

    dim3 grid(UNITS / 32, rows / 256);
    iso_main_kernel<<<grid, 256>>>(x, out);
}

// round 5
// speedup vs baseline: 1.8692x; 1.7462x over previous
#include <cuda_runtime.h>
#include <cuda_bf16.h>
#include <cstdint>

#define UNITS 256
#define NUM_BUCKETS 501
#define LB (-17.0f)
#define UB (8.0f)
#define STEPF 0.05f
#define INV_STEP 20.0f
#define RESIDUE (-17.05f)

// General-path table: per (unit, bucket):
//   .x = STEP * csum_exc[u][j] + RESIDUE + b[u]
//   .y = w[u][j] = relu(v[u][j])
__device__ float2 g_tab[UNITS * NUM_BUCKETS];

// Per-unit fast-path params:
//   .x = w (if w[u,:] constant over buckets), or -1.0f (non-constant -> gather)
//   .y = RESIDUE + b[u]
__device__ float2 g_param[UNITS];

// ---------------------------------------------------------------------------
// Kernel A: build table + detect constant-w units. One block per unit.
// ---------------------------------------------------------------------------
__global__ void build_table_kernel(const float* __restrict__ v,
                                   const float* __restrict__ b) {
    __shared__ float s[512];
    __shared__ float smin[512];
    __shared__ float smax[512];
    const int u = blockIdx.x;
    const int t = threadIdx.x;

    float w = 0.0f;
    if (t < NUM_BUCKETS) {
        w = fmaxf(v[u * NUM_BUCKETS + t], 0.0f);
    }
    s[t] = w;
    smin[t] = (t < NUM_BUCKETS) ? w :  1e30f;
    smax[t] = (t < NUM_BUCKETS) ? w : -1e30f;

    // inclusive scan (Hillis-Steele)
    #pragma unroll
    for (int off = 1; off < 512; off <<= 1) {
        __syncthreads();
        float add = (t >= off) ? s[t - off] : 0.0f;
        __syncthreads();
        s[t] += add;
    }

    // min/max reduction
    #pragma unroll
    for (int off = 256; off > 0; off >>= 1) {
        __syncthreads();
        if (t < off) {
            smin[t] = fminf(smin[t], smin[t + off]);
            smax[t] = fmaxf(smax[t], smax[t + off]);
        }
    }
    __syncthreads();

    const float bu = b[u];
    if (t < NUM_BUCKETS) {
        float inc = s[t];
        float exc = inc - w;           // exclusive cumsum
        float2 e;
        e.x = STEPF * exc + RESIDUE + bu;
        e.y = w;
        g_tab[u * NUM_BUCKETS + t] = e;
    }
    if (t == 0) {
        float2 p;
        p.x = (smin[0] == smax[0]) ? smin[0] : -1.0f;
        p.y = RESIDUE + bu;
        g_param[u] = p;
    }
}

// ---------------------------------------------------------------------------
// Kernel B: streaming main pass with per-unit fast path.
// Thread's column group (4 units) is fixed; grid-strides over rows so the
// per-unit params stay in registers. Fully coalesced float4 in/out.
// ---------------------------------------------------------------------------
__global__ void __launch_bounds__(256)
iso_main_kernel(const float4* __restrict__ x4,
                float4* __restrict__ out4,
                int rows) {
    const int gid    = blockIdx.x * 256 + threadIdx.x;
    const int col    = gid & 63;                 // float4 column (0..63)
    const int row0   = gid >> 6;
    const int rstride = (gridDim.x * 256) >> 6;
    const int ubase  = col * 4;

    // Per-unit params in registers
    float2 p0 = g_param[ubase + 0];
    float2 p1 = g_param[ubase + 1];
    float2 p2 = g_param[ubase + 2];
    float2 p3 = g_param[ubase + 3];
    const float pw[4]   = {p0.x, p1.x, p2.x, p3.x};
    const float pb[4]   = {p0.y, p1.y, p2.y, p3.y};

    for (int row = row0; row < rows; row += rstride) {
        const float4 xv = x4[row * 64 + col];
        float xin[4] = {xv.x, xv.y, xv.z, xv.w};
        float oo[4];

        #pragma unroll
        for (int j = 0; j < 4; ++j) {
            float xc = fminf(fmaxf(xin[j], LB + 1e-9f), UB - 1e-9f);
            float t  = xc - LB + STEPF;              // in (0.05, 25.05)

            float logit;
            if (pw[j] >= 0.0f) {
                // constant-w fast path: logit = w*t + (RESIDUE + b)
                logit = fmaf(t, pw[j], pb[j]);
            } else {
                // general path: table gather
                int idx = (int)(t * INV_STEP);
                idx = min(idx, NUM_BUCKETS - 1);
                float delta = t - (float)idx * STEPF;
                float2 tw = __ldg(&g_tab[(ubase + j) * NUM_BUCKETS + idx]);
                logit = fmaf(delta, tw.y, tw.x);
            }
            float e = __expf(-logit);
            oo[j] = __frcp_rn(1.0f + e);
        }

        out4[row * 64 + col] = make_float4(oo[0], oo[1], oo[2], oo[3]);
    }
}

// ---------------------------------------------------------------------------
extern "C" void kernel_launch(void* const* d_in, const int* in_sizes, int n_in,
                              void* d_out, int out_size) {
    const float* x = (const float*)d_in[0];   // (65536, 256)
    const float* v = (const float*)d_in[1];   // (256, 501)
    const float* b = (const float*)d_in[2];   // (256,)
    float* out = (float*)d_out;

    // Build the (unit, bucket) table + per-unit fast-path params
    build_table_kernel<<<UNITS, 512>>>(v, b);

    const int total = in_sizes[0];            // 65536 * 256
    const int rows  = total / UNITS;          // 65536

    // 2048 blocks x 256 threads -> 524288 threads -> 8 rows per thread
    const int blocks = 2048;
    iso_main_kernel<<<blocks, 256>>>((const float4*)x, (float4*)out, rows);
}